// round 1
// baseline (speedup 1.0000x reference)
#include <cuda_runtime.h>

#define DIM 256
#define MAXM 16384
#define MAXN 4096
#define BM 64
#define BN 128
#define BK 32
#define SMEM_BYTES ((DIM*BM + 2*BK*BN) * (int)sizeof(float))   // 64KB A + 2x16KB B = 96KB

// __device__ scratch (allocation-free rule)
__device__ float  g_VT[(size_t)DIM * MAXM];   // v transposed  [k][m]
__device__ float  g_WT[(size_t)DIM * MAXN];   // codebook transposed [k][n]
__device__ float  g_c2[MAXN];
__device__ float  g_v2[MAXM];
__device__ double g_loss;

__global__ void k_zero(double* p) { if (threadIdx.x == 0) *p = 0.0; }

// 32x32 smem tile transpose: src [R][DIM] row-major -> dst [DIM][R]
__global__ void k_transpose(const float* __restrict__ src, float* __restrict__ dst, int R) {
    __shared__ float tile[32][33];
    int kb = blockIdx.x * 32;
    int rb = blockIdx.y * 32;
    int tx = threadIdx.x, ty = threadIdx.y;
    #pragma unroll
    for (int j = 0; j < 32; j += 8)
        tile[ty + j][tx] = src[(size_t)(rb + ty + j) * DIM + kb + tx];
    __syncthreads();
    #pragma unroll
    for (int j = 0; j < 32; j += 8)
        dst[(size_t)(kb + ty + j) * R + rb + tx] = tile[tx][ty + j];
}

// per-row sum of squares (fp32, like reference) ; block (32,8)
__global__ void k_sumsq(const float* __restrict__ src, float* __restrict__ out, int R) {
    int row = blockIdx.x * 8 + threadIdx.y;
    if (row >= R) return;
    int lane = threadIdx.x;
    const float* p = src + (size_t)row * DIM;
    float s = 0.f;
    #pragma unroll
    for (int i = 0; i < DIM; i += 32) { float x = p[i + lane]; s = fmaf(x, x, s); }
    #pragma unroll
    for (int o = 16; o; o >>= 1) s += __shfl_xor_sync(0xffffffffu, s, o);
    if (lane == 0) out[row] = s;
}

__global__ void __launch_bounds__(256, 2)
k_vq_main(const float* __restrict__ v, const float* __restrict__ w,
          const float* __restrict__ VT, const float* __restrict__ WT,
          const float* __restrict__ c2, const float* __restrict__ v2,
          float* __restrict__ dout, double* __restrict__ lossAcc,
          int M, int N, long long idxBase)
{
    extern __shared__ float smem[];
    float* As = smem;                 // [256][64]
    float* Bs = smem + DIM * BM;      // 2 x [32][128]

    const int tid  = threadIdx.x;
    const int lane = tid & 31;
    const int rg   = tid >> 5;        // warp id = row group (8 rows each)
    const int cg   = lane;            // code group (4 codes each)
    const int row0 = blockIdx.x * BM;

    // Load A panel (64 rows x 256 k) from transposed V: coalesced, conflict-free
    #pragma unroll
    for (int j = 0; j < 16; j++) {
        int i  = tid + j * 256;
        int k  = i >> 4;
        int r4 = (i & 15) << 2;
        *(float4*)(As + k * BM + r4) =
            *(const float4*)(VT + (size_t)k * M + row0 + r4);
    }

    float v2r[8];
    #pragma unroll
    for (int r = 0; r < 8; r++) v2r[r] = __ldg(&v2[row0 + rg * 8 + r]);

    unsigned long long best[8];
    #pragma unroll
    for (int r = 0; r < 8; r++) best[r] = 0xFFFFFFFFFFFFFFFFULL;

    const int NT = N / BN;
    for (int nt = 0; nt < NT; nt++) {
        const int code0 = nt * BN;
        float acc[8][4];
        #pragma unroll
        for (int r = 0; r < 8; r++)
            #pragma unroll
            for (int c = 0; c < 4; c++) acc[r][c] = 0.f;

        // preload kt = 0
        #pragma unroll
        for (int j = 0; j < 4; j++) {
            int i  = tid + j * 256;
            int k  = i >> 5;
            int c4 = (i & 31) << 2;
            *(float4*)(Bs + k * BN + c4) =
                *(const float4*)(WT + (size_t)k * N + code0 + c4);
        }
        __syncthreads();

        #pragma unroll 1
        for (int kt = 0; kt < DIM / BK; kt++) {
            float4 pre[4];
            if (kt < DIM / BK - 1) {
                #pragma unroll
                for (int j = 0; j < 4; j++) {
                    int i  = tid + j * 256;
                    int k  = i >> 5;
                    int c4 = (i & 31) << 2;
                    pre[j] = *(const float4*)(WT + (size_t)((kt + 1) * BK + k) * N + code0 + c4);
                }
            }
            const float* Bcur = Bs + (kt & 1) * BK * BN;
            const int kb = kt * BK;
            #pragma unroll 8
            for (int kk = 0; kk < BK; kk++) {
                float4 a0 = *(const float4*)(As + (kb + kk) * BM + rg * 8);
                float4 a1 = *(const float4*)(As + (kb + kk) * BM + rg * 8 + 4);
                float4 b  = *(const float4*)(Bcur + kk * BN + cg * 4);
                float av[8] = {a0.x, a0.y, a0.z, a0.w, a1.x, a1.y, a1.z, a1.w};
                float bv[4] = {b.x, b.y, b.z, b.w};
                #pragma unroll
                for (int r = 0; r < 8; r++)
                    #pragma unroll
                    for (int c = 0; c < 4; c++)
                        acc[r][c] = fmaf(av[r], bv[c], acc[r][c]);
            }
            if (kt < DIM / BK - 1) {
                float* Bnxt = Bs + ((kt + 1) & 1) * BK * BN;
                #pragma unroll
                for (int j = 0; j < 4; j++) {
                    int i  = tid + j * 256;
                    int k  = i >> 5;
                    int c4 = (i & 31) << 2;
                    *(float4*)(Bnxt + k * BN + c4) = pre[j];
                }
            }
            __syncthreads();
        }

        // argmin epilogue for this N-tile: score = fp32((v2 - 2*dot) + c2), mimic ref op order
        #pragma unroll
        for (int c = 0; c < 4; c++) {
            int code = code0 + cg * 4 + c;
            float c2c = __ldg(&c2[code]);
            #pragma unroll
            for (int r = 0; r < 8; r++) {
                float score = __fadd_rn(__fsub_rn(v2r[r], __fmul_rn(2.0f, acc[r][c])), c2c);
                unsigned u = __float_as_uint(score);
                u = (u & 0x80000000u) ? ~u : (u | 0x80000000u);
                unsigned long long key = ((unsigned long long)u << 32) | (unsigned)code;
                if (code != 0 && key < best[r]) best[r] = key;   // code 0 excluded like ref
            }
        }
    }

    // warp-wide min (each warp owns rows rg*8 .. rg*8+7 fully)
    #pragma unroll
    for (int r = 0; r < 8; r++) {
        unsigned long long k = best[r];
        #pragma unroll
        for (int o = 16; o; o >>= 1) {
            unsigned long long other = __shfl_xor_sync(0xffffffffu, k, o);
            if (other < k) k = other;
        }
        best[r] = k;
    }

    // final epilogue: mask check, gather, write out/idx, loss accumulation
    double ls = 0.0;
    const float CEQ = 0.00390625f;  // 1/256, exactly representable
    #pragma unroll 1
    for (int r = 0; r < 8; r++) {
        int row  = row0 + rg * 8 + r;
        int code = (int)(best[r] & 0xFFFFFFFFULL);
        const float4* vr = (const float4*)(v + (size_t)row * DIM);
        float4 x0 = vr[lane * 2], x1 = vr[lane * 2 + 1];
        bool alleq = (x0.x == CEQ) && (x0.y == CEQ) && (x0.z == CEQ) && (x0.w == CEQ) &&
                     (x1.x == CEQ) && (x1.y == CEQ) && (x1.z == CEQ) && (x1.w == CEQ);
        if (__all_sync(0xffffffffu, alleq)) code = 0;

        const float4* cr = (const float4*)(w + (size_t)code * DIM);
        float4 o0 = cr[lane * 2], o1 = cr[lane * 2 + 1];
        float4* orow = (float4*)(dout + (size_t)row * DIM);
        orow[lane * 2]     = o0;
        orow[lane * 2 + 1] = o1;
        if (idxBase >= 0 && lane == 0) dout[idxBase + row] = (float)code;

        float d;
        d = o0.x - x0.x; ls += (double)d * d;
        d = o0.y - x0.y; ls += (double)d * d;
        d = o0.z - x0.z; ls += (double)d * d;
        d = o0.w - x0.w; ls += (double)d * d;
        d = o1.x - x1.x; ls += (double)d * d;
        d = o1.y - x1.y; ls += (double)d * d;
        d = o1.z - x1.z; ls += (double)d * d;
        d = o1.w - x1.w; ls += (double)d * d;
    }
    #pragma unroll
    for (int o = 16; o; o >>= 1) ls += __shfl_xor_sync(0xffffffffu, ls, o);
    if (lane == 0) atomicAdd(lossAcc, ls);
}

__global__ void k_fin(float* dout, const double* lossAcc,
                      long long lossPos, long long usedPos, double invCnt) {
    if (threadIdx.x == 0) {
        if (lossPos >= 0) dout[lossPos] = (float)(*lossAcc * invCnt);
        if (usedPos >= 0) dout[usedPos] = 0.0f;
    }
}

extern "C" void kernel_launch(void* const* d_in, const int* in_sizes, int n_in,
                              void* d_out, int out_size)
{
    const float* v = (const float*)d_in[0];
    const float* w = (const float*)d_in[1];
    const int M = in_sizes[0] / DIM;   // 16384
    const int N = in_sizes[1] / DIM;   // 4096
    float* out = (float*)d_out;

    float *pVT, *pWT, *pC2, *pV2; double* pLoss;
    cudaGetSymbolAddress((void**)&pVT, g_VT);
    cudaGetSymbolAddress((void**)&pWT, g_WT);
    cudaGetSymbolAddress((void**)&pC2, g_c2);
    cudaGetSymbolAddress((void**)&pV2, g_v2);
    cudaGetSymbolAddress((void**)&pLoss, g_loss);

    long long base = (long long)M * DIM;
    long long idxBase = -1, lossPos = -1, usedPos = -1;
    if ((long long)out_size >= base + M)     idxBase = base;
    if ((long long)out_size >= base + M + 1) lossPos = base + M;
    if ((long long)out_size >= base + M + 2) usedPos = base + M + 1;

    k_zero<<<1, 32>>>(pLoss);

    dim3 tb(32, 8);
    k_transpose<<<dim3(DIM / 32, M / 32), tb>>>(v, pVT, M);
    k_transpose<<<dim3(DIM / 32, N / 32), tb>>>(w, pWT, N);
    k_sumsq<<<(M + 7) / 8, tb>>>(v, pV2, M);
    k_sumsq<<<(N + 7) / 8, tb>>>(w, pC2, N);

    cudaFuncSetAttribute(k_vq_main, cudaFuncAttributeMaxDynamicSharedMemorySize, SMEM_BYTES);
    k_vq_main<<<M / BM, 256, SMEM_BYTES>>>(v, w, pVT, pWT, pC2, pV2,
                                           out, pLoss, M, N, idxBase);

    k_fin<<<1, 32>>>(out, pLoss, lossPos, usedPos, 1.0 / ((double)M * DIM));
}